// round 4
// baseline (speedup 1.0000x reference)
#include <cuda_runtime.h>
#include <math_constants.h>

#define BT      32768   // B*T rows
#define ZC      512     // input channels
#define DD      256     // embed dim
#define KCODES  8192    // codebook entries
#define NPART   1024    // loss partials

// scratch (allocation-free requirement -> __device__ globals)
__device__ float g_h[BT * DD];        // 32 MB: projected h
__device__ float g_cnorm[KCODES];     // fl32(||e_k||^2), fp64-accumulated
__device__ float g_hnorm[BT];         // fl32(||h_row||^2), fp64-accumulated
__device__ int   g_idx[BT];           // argmin index per row
__device__ float g_part[NPART];       // loss partial sums

// ---------------------------------------------------------------------------
// K1: h = x @ W + b   (fp32 FFMA, 128x128 tile, kchunk 16)
// ---------------------------------------------------------------------------
__global__ __launch_bounds__(256, 2)
void k_gemm_h(const float* __restrict__ x, const float* __restrict__ W,
              const float* __restrict__ b) {
    __shared__ float As[16][128];   // [k][m]  (transposed store)
    __shared__ float Bs[16][128];   // [k][n]
    const int tid = threadIdx.x;
    const int tx = tid & 15, ty = tid >> 4;
    const int m0 = blockIdx.y * 128;
    const int n0 = blockIdx.x * 128;

    float acc[8][8];
#pragma unroll
    for (int i = 0; i < 8; i++)
#pragma unroll
        for (int j = 0; j < 8; j++) acc[i][j] = 0.f;

    const int ar  = tid >> 2;        // 0..63
    const int ac4 = tid & 3;
    const int bkr = tid >> 5;        // 0..7
    const int bc4 = tid & 31;

    for (int k0 = 0; k0 < ZC; k0 += 16) {
        float4 a0 = *(const float4*)&x[(m0 + ar)      * ZC + k0 + ac4 * 4];
        float4 a1 = *(const float4*)&x[(m0 + ar + 64) * ZC + k0 + ac4 * 4];
        float4 w0 = *(const float4*)&W[(k0 + bkr)     * DD + n0 + bc4 * 4];
        float4 w1 = *(const float4*)&W[(k0 + bkr + 8) * DD + n0 + bc4 * 4];
        __syncthreads();
        As[ac4 * 4 + 0][ar]      = a0.x; As[ac4 * 4 + 1][ar]      = a0.y;
        As[ac4 * 4 + 2][ar]      = a0.z; As[ac4 * 4 + 3][ar]      = a0.w;
        As[ac4 * 4 + 0][ar + 64] = a1.x; As[ac4 * 4 + 1][ar + 64] = a1.y;
        As[ac4 * 4 + 2][ar + 64] = a1.z; As[ac4 * 4 + 3][ar + 64] = a1.w;
        *(float4*)&Bs[bkr][bc4 * 4]     = w0;
        *(float4*)&Bs[bkr + 8][bc4 * 4] = w1;
        __syncthreads();
#pragma unroll
        for (int kk = 0; kk < 16; kk++) {
            float4 av0 = *(const float4*)&As[kk][ty * 8];
            float4 av1 = *(const float4*)&As[kk][ty * 8 + 4];
            float4 bv0 = *(const float4*)&Bs[kk][tx * 8];
            float4 bv1 = *(const float4*)&Bs[kk][tx * 8 + 4];
            float a[8] = {av0.x, av0.y, av0.z, av0.w, av1.x, av1.y, av1.z, av1.w};
            float c[8] = {bv0.x, bv0.y, bv0.z, bv0.w, bv1.x, bv1.y, bv1.z, bv1.w};
#pragma unroll
            for (int i = 0; i < 8; i++)
#pragma unroll
                for (int j = 0; j < 8; j++) acc[i][j] = fmaf(a[i], c[j], acc[i][j]);
        }
    }
    float bias[8];
#pragma unroll
    for (int j = 0; j < 8; j++) bias[j] = b[n0 + tx * 8 + j];
#pragma unroll
    for (int i = 0; i < 8; i++) {
        int row = m0 + ty * 8 + i;
#pragma unroll
        for (int j = 0; j < 8; j++)
            g_h[row * DD + n0 + tx * 8 + j] = acc[i][j] + bias[j];
    }
}

// ---------------------------------------------------------------------------
// K2: B_k = fl32( ||e_k||^2 )  — fp64 accumulate (correctly rounded)
// ---------------------------------------------------------------------------
__global__ __launch_bounds__(256)
void k_cnorm(const float* __restrict__ cb) {
    int code = blockIdx.x * 8 + (threadIdx.x >> 5);
    int lane = threadIdx.x & 31;
    const float* row = cb + code * DD;
    double s = 0.0;
#pragma unroll
    for (int i = 0; i < DD / 32; i++) {
        double v = (double)row[lane + i * 32];
        s = fma(v, v, s);
    }
#pragma unroll
    for (int o = 16; o > 0; o >>= 1) s += __shfl_xor_sync(0xffffffffu, s, o);
    if (lane == 0) g_cnorm[code] = (float)s;
}

// ---------------------------------------------------------------------------
// K2b: A_row = fl32( ||h_row||^2 )  — fp64 accumulate
// ---------------------------------------------------------------------------
__global__ __launch_bounds__(256)
void k_hnorm() {
    int row  = blockIdx.x * 8 + (threadIdx.x >> 5);
    int lane = threadIdx.x & 31;
    const float* hr = g_h + (long)row * DD;
    double s = 0.0;
#pragma unroll
    for (int i = 0; i < DD / 32; i++) {
        double v = (double)hr[lane + i * 32];
        s = fma(v, v, s);
    }
#pragma unroll
    for (int o = 16; o > 0; o >>= 1) s += __shfl_xor_sync(0xffffffffu, s, o);
    if (lane == 0) g_hnorm[row] = (float)s;
}

// ---------------------------------------------------------------------------
// K3: argmin_k  fl32( fl32(A + B_k) - 2*M_k )   — reference rounding structure
//     fp32 SGEMM for M, lower-index tie-break everywhere (jnp.argmin rule).
// ---------------------------------------------------------------------------
__global__ __launch_bounds__(256, 2)
void k_argmin(const float* __restrict__ cb) {
    __shared__ float As[16][128];   // [d][m]  h tile (transposed)
    __shared__ float Bs[16][128];   // [d][c]  codebook tile (transposed)
    const int tid = threadIdx.x;
    const int tx = tid & 15, ty = tid >> 4;
    const int m0 = blockIdx.x * 128;

    float best[8];
    int   bidx[8];
    float hn[8];
#pragma unroll
    for (int i = 0; i < 8; i++) {
        best[i] = CUDART_INF_F; bidx[i] = 0;
        hn[i] = g_hnorm[m0 + ty * 8 + i];
    }

    const int r  = tid >> 2;   // 0..63
    const int c4 = tid & 3;

    for (int kt = 0; kt < KCODES; kt += 128) {
        float acc[8][8];
#pragma unroll
        for (int i = 0; i < 8; i++)
#pragma unroll
            for (int j = 0; j < 8; j++) acc[i][j] = 0.f;

        for (int d0 = 0; d0 < DD; d0 += 16) {
            float4 a0 = *(const float4*)&g_h[(m0 + r)      * DD + d0 + c4 * 4];
            float4 a1 = *(const float4*)&g_h[(m0 + r + 64) * DD + d0 + c4 * 4];
            float4 w0 = *(const float4*)&cb[(kt + r)       * DD + d0 + c4 * 4];
            float4 w1 = *(const float4*)&cb[(kt + r + 64)  * DD + d0 + c4 * 4];
            __syncthreads();
            As[c4 * 4 + 0][r]      = a0.x; As[c4 * 4 + 1][r]      = a0.y;
            As[c4 * 4 + 2][r]      = a0.z; As[c4 * 4 + 3][r]      = a0.w;
            As[c4 * 4 + 0][r + 64] = a1.x; As[c4 * 4 + 1][r + 64] = a1.y;
            As[c4 * 4 + 2][r + 64] = a1.z; As[c4 * 4 + 3][r + 64] = a1.w;
            Bs[c4 * 4 + 0][r]      = w0.x; Bs[c4 * 4 + 1][r]      = w0.y;
            Bs[c4 * 4 + 2][r]      = w0.z; Bs[c4 * 4 + 3][r]      = w0.w;
            Bs[c4 * 4 + 0][r + 64] = w1.x; Bs[c4 * 4 + 1][r + 64] = w1.y;
            Bs[c4 * 4 + 2][r + 64] = w1.z; Bs[c4 * 4 + 3][r + 64] = w1.w;
            __syncthreads();
#pragma unroll
            for (int kk = 0; kk < 16; kk++) {
                float4 av0 = *(const float4*)&As[kk][ty * 8];
                float4 av1 = *(const float4*)&As[kk][ty * 8 + 4];
                float4 bv0 = *(const float4*)&Bs[kk][tx * 8];
                float4 bv1 = *(const float4*)&Bs[kk][tx * 8 + 4];
                float a[8] = {av0.x, av0.y, av0.z, av0.w, av1.x, av1.y, av1.z, av1.w};
                float c[8] = {bv0.x, bv0.y, bv0.z, bv0.w, bv1.x, bv1.y, bv1.z, bv1.w};
#pragma unroll
                for (int i = 0; i < 8; i++)
#pragma unroll
                    for (int j = 0; j < 8; j++) acc[i][j] = fmaf(a[i], c[j], acc[i][j]);
            }
        }
        // epilogue with the reference's two fp32 roundings at magnitude ~257:
        //   t = fl32(A + B_k)            (ulp ~3.05e-5 grid)
        //   s = fl32(t - 2*M_k)          (2*M exact; fused == unfused)
#pragma unroll
        for (int j = 0; j < 8; j++) {
            int code = kt + tx * 8 + j;
            float cn = g_cnorm[code];
#pragma unroll
            for (int i = 0; i < 8; i++) {
                float t = __fadd_rn(hn[i], cn);
                float s = __fmaf_rn(-2.0f, acc[i][j], t);
                // strict < keeps the earliest (lowest) code this thread saw
                if (s < best[i]) { best[i] = s; bidx[i] = code; }
            }
        }
    }
    // reduce across the 16 tx threads sharing each row; tie -> lower index
#pragma unroll
    for (int i = 0; i < 8; i++) {
        float v = best[i];
        int   bi = bidx[i];
#pragma unroll
        for (int off = 8; off >= 1; off >>= 1) {
            float ov = __shfl_xor_sync(0xffffffffu, v, off);
            int   oi = __shfl_xor_sync(0xffffffffu, bi, off);
            if (ov < v || (ov == v && oi < bi)) { v = ov; bi = oi; }
        }
        if (tx == 0) g_idx[m0 + ty * 8 + i] = bi;
    }
}

// ---------------------------------------------------------------------------
// K4: gather zq -> out, partial loss sums  (deterministic: fixed order)
// ---------------------------------------------------------------------------
__global__ __launch_bounds__(256)
void k_gather(const float* __restrict__ cb, float* __restrict__ out) {
    __shared__ float red[256];
    float lsum = 0.f;
    const int total = BT * DD;
    for (int e = blockIdx.x * 256 + threadIdx.x; e < total; e += NPART * 256) {
        int row = e >> 8;
        int d = e & (DD - 1);
        int c = g_idx[row];
        float zq = cb[c * DD + d];
        float hh = g_h[e];
        out[e] = zq;                         // STE forward value == zq
        float df = zq - hh;
        lsum = fmaf(df, df, lsum);
    }
    red[threadIdx.x] = lsum;
    __syncthreads();
    for (int o = 128; o > 0; o >>= 1) {
        if (threadIdx.x < o) red[threadIdx.x] += red[threadIdx.x + o];
        __syncthreads();
    }
    if (threadIdx.x == 0) g_part[blockIdx.x] = red[0];
}

// ---------------------------------------------------------------------------
// K5: final loss reduce -> out[out_size-1]
// ---------------------------------------------------------------------------
__global__ __launch_bounds__(256)
void k_loss(float* __restrict__ out, int out_size) {
    __shared__ float red[256];
    float s = 0.f;
    for (int i = threadIdx.x; i < NPART; i += 256) s += g_part[i];
    red[threadIdx.x] = s;
    __syncthreads();
    for (int o = 128; o > 0; o >>= 1) {
        if (threadIdx.x < o) red[threadIdx.x] += red[threadIdx.x + o];
        __syncthreads();
    }
    if (threadIdx.x == 0)
        out[out_size - 1] = 1.25f * red[0] / (float)(BT * DD);
}

// ---------------------------------------------------------------------------
extern "C" void kernel_launch(void* const* d_in, const int* in_sizes, int n_in,
                              void* d_out, int out_size) {
    const float* x  = (const float*)d_in[0];   // [8,4096,1,512]
    const float* W  = (const float*)d_in[1];   // [512,256]
    const float* b  = (const float*)d_in[2];   // [256]
    const float* cb = (const float*)d_in[3];   // [8192,256]
    float* out = (float*)d_out;

    k_gemm_h<<<dim3(DD / 128, BT / 128), 256>>>(x, W, b);
    k_cnorm<<<KCODES / 8, 256>>>(cb);
    k_hnorm<<<BT / 8, 256>>>();
    k_argmin<<<BT / 128, 256>>>(cb);
    k_gather<<<NPART, 256>>>(cb, out);
    k_loss<<<1, 256>>>(out, out_size);
}